// round 1
// baseline (speedup 1.0000x reference)
#include <cuda_runtime.h>
#include <math.h>

#define TB   1024     // tokens = B*S
#define HD   1024     // hidden
#define NHQ  16
#define NHKV 4
#define DH   64
#define SEQ  512
#define NB   2
#define NE   8
#define ID   4096
#define GRP  (NHQ / NHKV)

// ---------------- scratch (device globals; allocation-free) ----------------
__device__ float g_h [TB * HD];
__device__ float g_q [TB * NHQ * DH];
__device__ float g_k [TB * NHKV * DH];
__device__ float g_v [TB * NHKV * DH];
__device__ float g_sc[(size_t)NB * NHQ * SEQ * SEQ];   // 33.5 MB
__device__ float g_ao[TB * NHQ * DH];
__device__ float g_x2[TB * HD];
__device__ float g_t [TB * HD];
__device__ int   g_cnt[NE];
__device__ int   g_rows[NE * TB];
__device__ int   g_se[TB * 2];
__device__ int   g_sr[TB * 2];
__device__ float g_sp[TB * 2];
__device__ float g_act[(size_t)NE * TB * ID];          // 128 MB
__device__ float g_dn [(size_t)NE * TB * HD];          // 33.5 MB

// ---------------- RMSNorm ----------------
__device__ __forceinline__ void rms_body(const float* __restrict__ x,
                                         const float* __restrict__ w,
                                         float* __restrict__ o)
{
    const int t = blockIdx.x;
    const float* xr = x + (size_t)t * HD;
    const int tid = threadIdx.x;
    float s = 0.f;
    for (int i = tid; i < HD; i += 256) { float v = xr[i]; s += v * v; }
    __shared__ float red[256];
    red[tid] = s; __syncthreads();
    for (int st = 128; st > 0; st >>= 1) {
        if (tid < st) red[tid] += red[tid + st];
        __syncthreads();
    }
    const float inv = rsqrtf(red[0] * (1.f / 1024.f) + 1.1920929e-07f);
    for (int i = tid; i < HD; i += 256)
        o[(size_t)t * HD + i] = xr[i] * inv * w[i];
}

__global__ void __launch_bounds__(256) k_rms1(const float* x, const float* w) { rms_body(x, w, g_h); }
__global__ void __launch_bounds__(256) k_rms2(const float* w)                 { rms_body(g_x2, w, g_t); }

// ---------------- generic 128x64x16 fp32 GEMM body ----------------
// C[M,N] = A[M,K] @ B[K,N] + bias + resid.  256 threads, 8x4 per thread.
__device__ __forceinline__ void gemm128x64_body(
    const float* __restrict__ A, int lda,
    const float* __restrict__ B, int N,
    const float* __restrict__ bias,
    const float* __restrict__ resid,
    float* __restrict__ C,
    int M, int K)
{
    __shared__ float As[16][136];
    __shared__ float Bs[16][64];
    const int bm = blockIdx.y * 128;
    const int bn = blockIdx.x * 64;
    const int tid = threadIdx.x;
    const int tx = tid & 15, ty = tid >> 4;
    float acc[8][4];
#pragma unroll
    for (int i = 0; i < 8; i++)
#pragma unroll
        for (int j = 0; j < 4; j++) acc[i][j] = 0.f;

    for (int k0 = 0; k0 < K; k0 += 16) {
#pragma unroll
        for (int l = 0; l < 8; l++) {
            int idx = tid + l * 256;
            int r = idx >> 4, c = idx & 15;
            int gr = bm + r;
            As[c][r] = (gr < M) ? A[(size_t)gr * lda + k0 + c] : 0.f;
        }
#pragma unroll
        for (int l = 0; l < 4; l++) {
            int idx = tid + l * 256;
            int r = idx >> 6, c = idx & 63;
            Bs[r][c] = B[(size_t)(k0 + r) * N + bn + c];
        }
        __syncthreads();
#pragma unroll
        for (int kk = 0; kk < 16; kk++) {
            float4 b4 = *(const float4*)&Bs[kk][tx * 4];
            float4 a0 = *(const float4*)&As[kk][ty * 8];
            float4 a1 = *(const float4*)&As[kk][ty * 8 + 4];
            float av[8] = {a0.x, a0.y, a0.z, a0.w, a1.x, a1.y, a1.z, a1.w};
            float bv[4] = {b4.x, b4.y, b4.z, b4.w};
#pragma unroll
            for (int i = 0; i < 8; i++)
#pragma unroll
                for (int j = 0; j < 4; j++)
                    acc[i][j] = fmaf(av[i], bv[j], acc[i][j]);
        }
        __syncthreads();
    }
#pragma unroll
    for (int i = 0; i < 8; i++) {
        int r = bm + ty * 8 + i;
        if (r >= M) continue;
#pragma unroll
        for (int j = 0; j < 4; j++) {
            int c = bn + tx * 4 + j;
            float v = acc[i][j];
            if (bias)  v += bias[c];
            if (resid) v += resid[(size_t)r * N + c];
            C[(size_t)r * N + c] = v;
        }
    }
}

__global__ void __launch_bounds__(256) k_gemm_q(const float* w, const float* b) {
    gemm128x64_body(g_h, HD, w, NHQ * DH, b, nullptr, g_q, TB, HD);
}
__global__ void __launch_bounds__(256) k_gemm_k(const float* w, const float* b) {
    gemm128x64_body(g_h, HD, w, NHKV * DH, b, nullptr, g_k, TB, HD);
}
__global__ void __launch_bounds__(256) k_gemm_v(const float* w, const float* b) {
    gemm128x64_body(g_h, HD, w, NHKV * DH, b, nullptr, g_v, TB, HD);
}
__global__ void __launch_bounds__(256) k_gemm_o(const float* w, const float* b, const float* resid) {
    gemm128x64_body(g_ao, NHQ * DH, w, HD, b, resid, g_x2, TB, NHQ * DH);
}

// ---------------- attention: scores = Q @ K^T * scale ----------------
__global__ void __launch_bounds__(256) k_attn_scores()
{
    const int bh = blockIdx.z;
    const int b = bh / NHQ, h = bh % NHQ, hk = h / GRP;
    const int s0 = blockIdx.y * 64, t0 = blockIdx.x * 64;
    __shared__ float Qs[64][68];   // [d][s]
    __shared__ float Ks[64][68];   // [d][t]
    const int tid = threadIdx.x, tx = tid & 15, ty = tid >> 4;
#pragma unroll
    for (int l = 0; l < 16; l++) {
        int idx = tid + l * 256;
        int r = idx >> 6, c = idx & 63;
        Qs[c][r] = g_q[((size_t)(b * SEQ + s0 + r) * NHQ  + h ) * DH + c];
        Ks[c][r] = g_k[((size_t)(b * SEQ + t0 + r) * NHKV + hk) * DH + c];
    }
    __syncthreads();
    float acc[4][4];
#pragma unroll
    for (int i = 0; i < 4; i++)
#pragma unroll
        for (int j = 0; j < 4; j++) acc[i][j] = 0.f;
#pragma unroll 16
    for (int d = 0; d < 64; d++) {
        float4 a  = *(const float4*)&Qs[d][ty * 4];
        float4 b4 = *(const float4*)&Ks[d][tx * 4];
        float av[4] = {a.x, a.y, a.z, a.w};
        float bv[4] = {b4.x, b4.y, b4.z, b4.w};
#pragma unroll
        for (int i = 0; i < 4; i++)
#pragma unroll
            for (int j = 0; j < 4; j++)
                acc[i][j] = fmaf(av[i], bv[j], acc[i][j]);
    }
    float* outp = g_sc + ((size_t)bh * SEQ + s0) * SEQ + t0;
#pragma unroll
    for (int i = 0; i < 4; i++)
#pragma unroll
        for (int j = 0; j < 4; j++)
            outp[(size_t)(ty * 4 + i) * SEQ + tx * 4 + j] = acc[i][j] * 0.125f;
}

// ---------------- softmax over 512-wide rows ----------------
__global__ void __launch_bounds__(256) k_softmax()
{
    float* p = g_sc + (size_t)blockIdx.x * SEQ;
    const int tid = threadIdx.x;
    float a = p[tid], b = p[tid + 256];
    __shared__ float red[256];
    red[tid] = fmaxf(a, b); __syncthreads();
    for (int s = 128; s > 0; s >>= 1) {
        if (tid < s) red[tid] = fmaxf(red[tid], red[tid + s]);
        __syncthreads();
    }
    const float m = red[0];
    __syncthreads();
    float ea = __expf(a - m), eb = __expf(b - m);
    red[tid] = ea + eb; __syncthreads();
    for (int s = 128; s > 0; s >>= 1) {
        if (tid < s) red[tid] += red[tid + s];
        __syncthreads();
    }
    const float inv = 1.f / red[0];
    p[tid] = ea * inv;
    p[tid + 256] = eb * inv;
}

// ---------------- attention: O = P @ V ----------------
__global__ void __launch_bounds__(256) k_attn_pv()
{
    const int bh = blockIdx.y;
    const int b = bh / NHQ, h = bh % NHQ, hk = h / GRP;
    const int s0 = blockIdx.x * 64;
    __shared__ float Ps[64][68];   // [t][s]
    __shared__ float Vs[64][68];   // [t][d]
    const int tid = threadIdx.x, tx = tid & 15, ty = tid >> 4;
    float acc[4][4];
#pragma unroll
    for (int i = 0; i < 4; i++)
#pragma unroll
        for (int j = 0; j < 4; j++) acc[i][j] = 0.f;
    const float* srow = g_sc + ((size_t)bh * SEQ + s0) * SEQ;
    for (int t0 = 0; t0 < SEQ; t0 += 64) {
#pragma unroll
        for (int l = 0; l < 16; l++) {
            int idx = tid + l * 256;
            int r = idx >> 6, c = idx & 63;
            Ps[c][r] = srow[(size_t)r * SEQ + t0 + c];
            Vs[r][c] = g_v[((size_t)(b * SEQ + t0 + r) * NHKV + hk) * DH + c];
        }
        __syncthreads();
#pragma unroll 16
        for (int t = 0; t < 64; t++) {
            float4 a  = *(const float4*)&Ps[t][ty * 4];
            float4 b4 = *(const float4*)&Vs[t][tx * 4];
            float av[4] = {a.x, a.y, a.z, a.w};
            float bv[4] = {b4.x, b4.y, b4.z, b4.w};
#pragma unroll
            for (int i = 0; i < 4; i++)
#pragma unroll
                for (int j = 0; j < 4; j++)
                    acc[i][j] = fmaf(av[i], bv[j], acc[i][j]);
        }
        __syncthreads();
    }
#pragma unroll
    for (int i = 0; i < 4; i++) {
        int s = s0 + ty * 4 + i;
#pragma unroll
        for (int j = 0; j < 4; j++) {
            int d = tx * 4 + j;
            g_ao[((size_t)(b * SEQ + s) * NHQ + h) * DH + d] = acc[i][j];
        }
    }
}

// ---------------- router: logits, top-2, softmax, scatter ----------------
__global__ void k_zero() { if (threadIdx.x < NE) g_cnt[threadIdx.x] = 0; }

__global__ void __launch_bounds__(256) k_router(const float* __restrict__ rw,
                                                const float* __restrict__ rb)
{
    const int t = blockIdx.x;
    const float* x = g_t + (size_t)t * HD;
    const int tid = threadIdx.x;
    const int e = tid & 7, ch = tid >> 3;        // 32 chunks of 32
    float s = 0.f;
    const int base = ch * 32;
    for (int i = base; i < base + 32; i++) s += x[i] * rw[i * NE + e];
    __shared__ float part[32][9];
    __shared__ float sl[8];
    part[ch][e] = s; __syncthreads();
    if (tid < 8) {
        float l = rb[tid];
        for (int c2 = 0; c2 < 32; c2++) l += part[c2][tid];
        sl[tid] = l;
    }
    __syncthreads();
    if (tid == 0) {
        int e0 = 0; float v0 = sl[0];
        for (int i = 1; i < 8; i++) if (sl[i] > v0) { v0 = sl[i]; e0 = i; }
        int e1 = -1; float v1 = -3.402823e38f;
        for (int i = 0; i < 8; i++) {
            if (i == e0) continue;
            if (sl[i] > v1) { v1 = sl[i]; e1 = i; }
        }
        const float z = __expf(v1 - v0);          // v1 <= v0
        const float p0 = 1.f / (1.f + z);
        const float p1 = z   / (1.f + z);
        const int r0 = atomicAdd(&g_cnt[e0], 1);
        const int r1 = atomicAdd(&g_cnt[e1], 1);
        g_rows[e0 * TB + r0] = t;
        g_rows[e1 * TB + r1] = t;
        g_se[t * 2 + 0] = e0; g_sr[t * 2 + 0] = r0; g_sp[t * 2 + 0] = p0;
        g_se[t * 2 + 1] = e1; g_sr[t * 2 + 1] = r1; g_sp[t * 2 + 1] = p1;
    }
}

// ---------------- MoE gate+up fused GEMM (gathered rows) ----------------
__global__ void __launch_bounds__(256) k_gateup(const float* __restrict__ gw,
                                                const float* __restrict__ gb,
                                                const float* __restrict__ uw,
                                                const float* __restrict__ ub)
{
    const int e = blockIdx.z;
    const int cnt = g_cnt[e];
    const int rm = blockIdx.y * 128;
    if (rm >= cnt) return;
    const int bn = blockIdx.x * 64;
    __shared__ float As[16][136];
    __shared__ float Bg[16][64];
    __shared__ float Bu[16][64];
    __shared__ int srow[128];
    const int tid = threadIdx.x, tx = tid & 15, ty = tid >> 4;
    if (tid < 128) {
        int rr = rm + tid;
        srow[tid] = (rr < cnt) ? g_rows[e * TB + rr] : -1;
    }
    __syncthreads();
    const float* Bgp = gw + (size_t)e * HD * ID;
    const float* Bup = uw + (size_t)e * HD * ID;
    float accg[8][4], accu[8][4];
#pragma unroll
    for (int i = 0; i < 8; i++)
#pragma unroll
        for (int j = 0; j < 4; j++) { accg[i][j] = 0.f; accu[i][j] = 0.f; }

    for (int k0 = 0; k0 < HD; k0 += 16) {
#pragma unroll
        for (int l = 0; l < 8; l++) {
            int idx = tid + l * 256;
            int r = idx >> 4, c = idx & 15;
            int tok = srow[r];
            As[c][r] = (tok >= 0) ? g_t[(size_t)tok * HD + k0 + c] : 0.f;
        }
#pragma unroll
        for (int l = 0; l < 4; l++) {
            int idx = tid + l * 256;
            int r = idx >> 6, c = idx & 63;
            size_t off = (size_t)(k0 + r) * ID + bn + c;
            Bg[r][c] = Bgp[off];
            Bu[r][c] = Bup[off];
        }
        __syncthreads();
#pragma unroll
        for (int kk = 0; kk < 16; kk++) {
            float4 bg = *(const float4*)&Bg[kk][tx * 4];
            float4 bu = *(const float4*)&Bu[kk][tx * 4];
            float4 a0 = *(const float4*)&As[kk][ty * 8];
            float4 a1 = *(const float4*)&As[kk][ty * 8 + 4];
            float av[8]  = {a0.x, a0.y, a0.z, a0.w, a1.x, a1.y, a1.z, a1.w};
            float bgv[4] = {bg.x, bg.y, bg.z, bg.w};
            float buv[4] = {bu.x, bu.y, bu.z, bu.w};
#pragma unroll
            for (int i = 0; i < 8; i++)
#pragma unroll
                for (int j = 0; j < 4; j++) {
                    accg[i][j] = fmaf(av[i], bgv[j], accg[i][j]);
                    accu[i][j] = fmaf(av[i], buv[j], accu[i][j]);
                }
        }
        __syncthreads();
    }
#pragma unroll
    for (int i = 0; i < 8; i++) {
        int r = rm + ty * 8 + i;
        if (r >= cnt) continue;
#pragma unroll
        for (int j = 0; j < 4; j++) {
            int c = bn + tx * 4 + j;
            float g = accg[i][j] + gb[(size_t)e * ID + c];
            float u = accu[i][j] + ub[(size_t)e * ID + c];
            float sg = g / (1.f + __expf(-g));       // silu
            g_act[((size_t)e * TB + r) * ID + c] = sg * u;
        }
    }
}

// ---------------- MoE down GEMM (packed rows) ----------------
__global__ void __launch_bounds__(256) k_down(const float* __restrict__ dw,
                                              const float* __restrict__ db)
{
    const int e = blockIdx.z;
    const int cnt = g_cnt[e];
    const int rm = blockIdx.y * 128;
    if (rm >= cnt) return;
    const int bn = blockIdx.x * 64;
    __shared__ float As[16][136];
    __shared__ float Bs[16][64];
    const int tid = threadIdx.x, tx = tid & 15, ty = tid >> 4;
    const float* Bp = dw + (size_t)e * ID * HD;
    const float* Ap = g_act + (size_t)e * TB * ID;
    float acc[8][4];
#pragma unroll
    for (int i = 0; i < 8; i++)
#pragma unroll
        for (int j = 0; j < 4; j++) acc[i][j] = 0.f;

    for (int k0 = 0; k0 < ID; k0 += 16) {
#pragma unroll
        for (int l = 0; l < 8; l++) {
            int idx = tid + l * 256;
            int r = idx >> 4, c = idx & 15;
            int gr = rm + r;
            As[c][r] = (gr < cnt) ? Ap[(size_t)gr * ID + k0 + c] : 0.f;
        }
#pragma unroll
        for (int l = 0; l < 4; l++) {
            int idx = tid + l * 256;
            int r = idx >> 6, c = idx & 63;
            Bs[r][c] = Bp[(size_t)(k0 + r) * HD + bn + c];
        }
        __syncthreads();
#pragma unroll
        for (int kk = 0; kk < 16; kk++) {
            float4 b4 = *(const float4*)&Bs[kk][tx * 4];
            float4 a0 = *(const float4*)&As[kk][ty * 8];
            float4 a1 = *(const float4*)&As[kk][ty * 8 + 4];
            float av[8] = {a0.x, a0.y, a0.z, a0.w, a1.x, a1.y, a1.z, a1.w};
            float bv[4] = {b4.x, b4.y, b4.z, b4.w};
#pragma unroll
            for (int i = 0; i < 8; i++)
#pragma unroll
                for (int j = 0; j < 4; j++)
                    acc[i][j] = fmaf(av[i], bv[j], acc[i][j]);
        }
        __syncthreads();
    }
#pragma unroll
    for (int i = 0; i < 8; i++) {
        int r = rm + ty * 8 + i;
        if (r >= cnt) continue;
#pragma unroll
        for (int j = 0; j < 4; j++) {
            int c = bn + tx * 4 + j;
            g_dn[((size_t)e * TB + r) * HD + c] = acc[i][j] + db[(size_t)e * HD + c];
        }
    }
}

// ---------------- combine: out = x2 + p0*dn0 + p1*dn1 ----------------
__global__ void __launch_bounds__(256) k_combine(float* __restrict__ out)
{
    const int t = blockIdx.x;
    const int tid = threadIdx.x;
    const int e0 = g_se[t * 2 + 0], r0 = g_sr[t * 2 + 0];
    const int e1 = g_se[t * 2 + 1], r1 = g_sr[t * 2 + 1];
    const float p0 = g_sp[t * 2 + 0], p1 = g_sp[t * 2 + 1];
    const float* d0 = g_dn + ((size_t)e0 * TB + r0) * HD;
    const float* d1 = g_dn + ((size_t)e1 * TB + r1) * HD;
    const float* xr = g_x2 + (size_t)t * HD;
    for (int i = tid; i < HD; i += 256)
        out[(size_t)t * HD + i] = xr[i] + p0 * d0[i] + p1 * d1[i];
}

// ---------------- launcher ----------------
extern "C" void kernel_launch(void* const* d_in, const int* in_sizes, int n_in,
                              void* d_out, int out_size)
{
    (void)in_sizes; (void)n_in; (void)out_size;
    const float* x   = (const float*)d_in[0];
    const float* n1w = (const float*)d_in[1];
    const float* qw  = (const float*)d_in[2];
    const float* qb  = (const float*)d_in[3];
    const float* kw  = (const float*)d_in[4];
    const float* kb  = (const float*)d_in[5];
    const float* vw  = (const float*)d_in[6];
    const float* vb  = (const float*)d_in[7];
    const float* ow  = (const float*)d_in[8];
    const float* ob  = (const float*)d_in[9];
    const float* n2w = (const float*)d_in[10];
    const float* rw  = (const float*)d_in[11];
    const float* rb  = (const float*)d_in[12];
    const float* gw  = (const float*)d_in[13];
    const float* gb  = (const float*)d_in[14];
    const float* uw  = (const float*)d_in[15];
    const float* ub  = (const float*)d_in[16];
    const float* dw  = (const float*)d_in[17];
    const float* db  = (const float*)d_in[18];
    float* out = (float*)d_out;

    k_rms1<<<TB, 256>>>(x, n1w);
    k_gemm_q<<<dim3(16, 8), 256>>>(qw, qb);
    k_gemm_k<<<dim3(4, 8), 256>>>(kw, kb);
    k_gemm_v<<<dim3(4, 8), 256>>>(vw, vb);
    k_attn_scores<<<dim3(SEQ / 64, SEQ / 64, NB * NHQ), 256>>>();
    k_softmax<<<NB * NHQ * SEQ, 256>>>();
    k_attn_pv<<<dim3(SEQ / 64, NB * NHQ), 256>>>();
    k_gemm_o<<<dim3(16, 8), 256>>>(ow, ob, x);
    k_rms2<<<TB, 256>>>(n2w);
    k_zero<<<1, 32>>>();
    k_router<<<TB, 256>>>(rw, rb);
    k_gateup<<<dim3(ID / 64, TB / 128, NE), 256>>>(gw, gb, uw, ub);
    k_down<<<dim3(HD / 64, TB / 128, NE), 256>>>(dw, db);
    k_combine<<<TB, 256>>>(out);
}

// round 2
// speedup vs baseline: 2.1290x; 2.1290x over previous
#include <cuda_runtime.h>
#include <math.h>
#include <stdint.h>

#define TB   1024     // tokens = B*S
#define HD   1024     // hidden
#define NHQ  16
#define NHKV 4
#define DH   64
#define SEQ  512
#define NB   2
#define NE   8
#define ID   4096
#define GRP  (NHQ / NHKV)

// ---------------- scratch (device globals; allocation-free) ----------------
__device__ float g_h [TB * HD];
__device__ float g_q [TB * NHQ * DH];
__device__ float g_k [TB * NHKV * DH];
__device__ float g_v [TB * NHKV * DH];
__device__ float g_sc[(size_t)NB * NHQ * SEQ * SEQ];
__device__ float g_ao[TB * NHQ * DH];
__device__ float g_x2[TB * HD];
__device__ float g_t [TB * HD];
__device__ int   g_cnt[NE];
__device__ int   g_rows[NE * TB];
__device__ int   g_se[TB * 2];
__device__ int   g_sr[TB * 2];
__device__ float g_sp[TB * 2];
__device__ float g_gt [(size_t)NE * TB * ID];   // gate pre-activation
__device__ float g_act[(size_t)NE * TB * ID];   // up, then silu(g)*u
__device__ float g_dn [(size_t)NE * TB * HD];

// ================= tf32 MMA block-GEMM core (128x128x16) =================
// 256 threads = 8 warps in 2x4; warp tile 64x32; atom m16n8k8.
// smem pitches: A pitch 20 floats, B pitch 136 floats (conflict-free for
// the fragment access patterns; verified mod-32 distinct).
#define PA 20
#define PB 136
#define AS_STAGE (128 * PA)   // 2560
#define BS_STAGE (16 * PB)    // 2176

__device__ __forceinline__ uint32_t tf32cvt(float x) {
    uint32_t u;
    asm("cvt.rna.tf32.f32 %0, %1;" : "=r"(u) : "f"(x));
    return u;
}

__device__ __forceinline__ void mma8(float* d, const uint32_t* a, uint32_t b0, uint32_t b1) {
    asm volatile("mma.sync.aligned.m16n8k8.row.col.f32.tf32.tf32.f32 "
                 "{%0,%1,%2,%3},{%4,%5,%6,%7},{%8,%9},{%0,%1,%2,%3};"
                 : "+f"(d[0]), "+f"(d[1]), "+f"(d[2]), "+f"(d[3])
                 : "r"(a[0]), "r"(a[1]), "r"(a[2]), "r"(a[3]), "r"(b0), "r"(b1));
}

// acc[matom][natom][reg]; srow: optional shared gather table (128 entries, clamped)
__device__ __forceinline__ void gemm_mainloop(
    float (&acc)[4][4][4],
    const float* __restrict__ A, int lda, const int* srow, int bm,
    const float* __restrict__ B, int ldb, int bn, int K,
    uint32_t* As, uint32_t* Bs)
{
    const int tid  = threadIdx.x;
    const int lane = tid & 31;
    const int warp = tid >> 5;
    const int wm = warp >> 2, wn = warp & 3;

#pragma unroll
    for (int i = 0; i < 4; i++)
#pragma unroll
        for (int j = 0; j < 4; j++)
#pragma unroll
            for (int r = 0; r < 4; r++) acc[i][j][r] = 0.f;

    const int f0 = tid, f1 = tid + 256;
    const int ar0 = f0 >> 2, ac0 = (f0 & 3) << 2;
    const int ar1 = f1 >> 2, ac1 = (f1 & 3) << 2;
    const int gr0 = srow ? srow[ar0] : bm + ar0;
    const int gr1 = srow ? srow[ar1] : bm + ar1;
    const int bk0 = f0 >> 5, bc0 = (f0 & 31) << 2;
    const int bk1 = f1 >> 5, bc1 = (f1 & 31) << 2;
    const float* pa0 = A + (size_t)gr0 * lda + ac0;
    const float* pa1 = A + (size_t)gr1 * lda + ac1;
    const float* pb0 = B + (size_t)bk0 * ldb + bn + bc0;
    const float* pb1 = B + (size_t)bk1 * ldb + bn + bc1;

    float4 va0, va1, vb0, vb1;

    // prologue: stage 0
    va0 = *(const float4*)(pa0);
    va1 = *(const float4*)(pa1);
    vb0 = *(const float4*)(pb0);
    vb1 = *(const float4*)(pb1);
    {
        uint32_t* dst = As;
        dst[ar0 * PA + ac0 + 0] = tf32cvt(va0.x); dst[ar0 * PA + ac0 + 1] = tf32cvt(va0.y);
        dst[ar0 * PA + ac0 + 2] = tf32cvt(va0.z); dst[ar0 * PA + ac0 + 3] = tf32cvt(va0.w);
        dst[ar1 * PA + ac1 + 0] = tf32cvt(va1.x); dst[ar1 * PA + ac1 + 1] = tf32cvt(va1.y);
        dst[ar1 * PA + ac1 + 2] = tf32cvt(va1.z); dst[ar1 * PA + ac1 + 3] = tf32cvt(va1.w);
        uint32_t* db = Bs;
        db[bk0 * PB + bc0 + 0] = tf32cvt(vb0.x); db[bk0 * PB + bc0 + 1] = tf32cvt(vb0.y);
        db[bk0 * PB + bc0 + 2] = tf32cvt(vb0.z); db[bk0 * PB + bc0 + 3] = tf32cvt(vb0.w);
        db[bk1 * PB + bc1 + 0] = tf32cvt(vb1.x); db[bk1 * PB + bc1 + 1] = tf32cvt(vb1.y);
        db[bk1 * PB + bc1 + 2] = tf32cvt(vb1.z); db[bk1 * PB + bc1 + 3] = tf32cvt(vb1.w);
    }
    __syncthreads();

    const int nst = K >> 4;
    for (int s = 0; s < nst; s++) {
        const int buf = s & 1;
        const bool more = (s + 1 < nst);
        if (more) {
            const int k0 = (s + 1) << 4;
            va0 = *(const float4*)(pa0 + k0);
            va1 = *(const float4*)(pa1 + k0);
            vb0 = *(const float4*)(pb0 + (size_t)k0 * ldb);
            vb1 = *(const float4*)(pb1 + (size_t)k0 * ldb);
        }
        // compute on buf
        const uint32_t* pA = As + buf * AS_STAGE;
        const uint32_t* pBx = Bs + buf * BS_STAGE;
#pragma unroll
        for (int kk = 0; kk < 2; kk++) {
            uint32_t af[4][4];
            const int c0 = kk * 8 + (lane & 3);
#pragma unroll
            for (int im = 0; im < 4; im++) {
                const int r0 = wm * 64 + im * 16 + (lane >> 2);
                af[im][0] = pA[r0 * PA + c0];
                af[im][1] = pA[(r0 + 8) * PA + c0];
                af[im][2] = pA[r0 * PA + c0 + 4];
                af[im][3] = pA[(r0 + 8) * PA + c0 + 4];
            }
            const int kr = kk * 8 + (lane & 3);
#pragma unroll
            for (int in = 0; in < 4; in++) {
                const int nn = wn * 32 + in * 8 + (lane >> 2);
                uint32_t b0 = pBx[kr * PB + nn];
                uint32_t b1 = pBx[(kr + 4) * PB + nn];
#pragma unroll
                for (int im = 0; im < 4; im++)
                    mma8(acc[im][in], af[im], b0, b1);
            }
        }
        if (more) {
            uint32_t* dst = As + (buf ^ 1) * AS_STAGE;
            dst[ar0 * PA + ac0 + 0] = tf32cvt(va0.x); dst[ar0 * PA + ac0 + 1] = tf32cvt(va0.y);
            dst[ar0 * PA + ac0 + 2] = tf32cvt(va0.z); dst[ar0 * PA + ac0 + 3] = tf32cvt(va0.w);
            dst[ar1 * PA + ac1 + 0] = tf32cvt(va1.x); dst[ar1 * PA + ac1 + 1] = tf32cvt(va1.y);
            dst[ar1 * PA + ac1 + 2] = tf32cvt(va1.z); dst[ar1 * PA + ac1 + 3] = tf32cvt(va1.w);
            uint32_t* db = Bs + (buf ^ 1) * BS_STAGE;
            db[bk0 * PB + bc0 + 0] = tf32cvt(vb0.x); db[bk0 * PB + bc0 + 1] = tf32cvt(vb0.y);
            db[bk0 * PB + bc0 + 2] = tf32cvt(vb0.z); db[bk0 * PB + bc0 + 3] = tf32cvt(vb0.w);
            db[bk1 * PB + bc1 + 0] = tf32cvt(vb1.x); db[bk1 * PB + bc1 + 1] = tf32cvt(vb1.y);
            db[bk1 * PB + bc1 + 2] = tf32cvt(vb1.z); db[bk1 * PB + bc1 + 3] = tf32cvt(vb1.w);
        }
        __syncthreads();
    }
}

// epilogue position helpers
#define EPI_LOOP(body)                                                        \
    {                                                                         \
        const int lane = threadIdx.x & 31;                                    \
        const int warp = threadIdx.x >> 5;                                    \
        const int wm = warp >> 2, wn = warp & 3;                              \
        _Pragma("unroll")                                                     \
        for (int im = 0; im < 4; im++) {                                      \
            _Pragma("unroll")                                                 \
            for (int in = 0; in < 4; in++) {                                  \
                const int rl = wm * 64 + im * 16 + (lane >> 2);               \
                const int cl = wn * 32 + in * 8 + ((lane & 3) << 1);          \
                _Pragma("unroll")                                             \
                for (int h = 0; h < 2; h++) {                                 \
                    _Pragma("unroll")                                         \
                    for (int g2 = 0; g2 < 2; g2++) {                          \
                        const int row_l = rl + h * 8;                         \
                        const int col_l = cl + g2;                            \
                        const float val = acc[im][in][h * 2 + g2];            \
                        body                                                  \
                    }                                                         \
                }                                                             \
            }                                                                 \
        }                                                                     \
    }

// ---------------- RMSNorm ----------------
__device__ __forceinline__ void rms_body(const float* __restrict__ x,
                                         const float* __restrict__ w,
                                         float* __restrict__ o)
{
    const int t = blockIdx.x;
    const float* xr = x + (size_t)t * HD;
    const int tid = threadIdx.x;
    float s = 0.f;
    for (int i = tid; i < HD; i += 256) { float v = xr[i]; s += v * v; }
    __shared__ float red[256];
    red[tid] = s; __syncthreads();
    for (int st = 128; st > 0; st >>= 1) {
        if (tid < st) red[tid] += red[tid + st];
        __syncthreads();
    }
    const float inv = rsqrtf(red[0] * (1.f / 1024.f) + 1.1920929e-07f);
    for (int i = tid; i < HD; i += 256)
        o[(size_t)t * HD + i] = xr[i] * inv * w[i];
}

__global__ void __launch_bounds__(256) k_rms1(const float* x, const float* w) { rms_body(x, w, g_h); }
__global__ void __launch_bounds__(256) k_rms2(const float* w)                 { rms_body(g_x2, w, g_t); }

// ---------------- fused QKV projection (tf32 MMA) ----------------
__global__ void __launch_bounds__(256) k_qkv(
    const float* __restrict__ qw, const float* __restrict__ qb,
    const float* __restrict__ kw, const float* __restrict__ kb,
    const float* __restrict__ vw, const float* __restrict__ vb)
{
    __shared__ uint32_t As[2 * AS_STAGE];
    __shared__ uint32_t Bs[2 * BS_STAGE];
    const int tile = blockIdx.x;           // 0..11
    const int bm = blockIdx.y * 128;
    const float* W; const float* bias; float* out; int ldo; int bn;
    if (tile < 8)       { W = qw; bias = qb; out = g_q; ldo = NHQ * DH;  bn = tile * 128; }
    else if (tile < 10) { W = kw; bias = kb; out = g_k; ldo = NHKV * DH; bn = (tile - 8) * 128; }
    else                { W = vw; bias = vb; out = g_v; ldo = NHKV * DH; bn = (tile - 10) * 128; }

    float acc[4][4][4];
    gemm_mainloop(acc, g_h, HD, nullptr, bm, W, ldo, bn, HD, As, Bs);

    EPI_LOOP({
        const int r = bm + row_l;
        const int c = bn + col_l;
        out[(size_t)r * ldo + c] = val + bias[c];
    })
}

// ---------------- O projection + residual (tf32 MMA) ----------------
__global__ void __launch_bounds__(256) k_oproj(
    const float* __restrict__ ow, const float* __restrict__ ob,
    const float* __restrict__ x)
{
    __shared__ uint32_t As[2 * AS_STAGE];
    __shared__ uint32_t Bs[2 * BS_STAGE];
    const int bm = blockIdx.y * 128;
    const int bn = blockIdx.x * 128;
    float acc[4][4][4];
    gemm_mainloop(acc, g_ao, NHQ * DH, nullptr, bm, ow, HD, bn, NHQ * DH, As, Bs);
    EPI_LOOP({
        const int r = bm + row_l;
        const int c = bn + col_l;
        g_x2[(size_t)r * HD + c] = val + ob[c] + x[(size_t)r * HD + c];
    })
}

// ---------------- attention: scores = Q @ K^T * scale (SIMT) ----------------
__global__ void __launch_bounds__(256) k_attn_scores()
{
    const int bh = blockIdx.z;
    const int b = bh / NHQ, h = bh % NHQ, hk = h / GRP;
    const int s0 = blockIdx.y * 64, t0 = blockIdx.x * 64;
    __shared__ float Qs[64][68];
    __shared__ float Ks[64][68];
    const int tid = threadIdx.x, tx = tid & 15, ty = tid >> 4;
#pragma unroll
    for (int l = 0; l < 16; l++) {
        int idx = tid + l * 256;
        int r = idx >> 6, c = idx & 63;
        Qs[c][r] = g_q[((size_t)(b * SEQ + s0 + r) * NHQ  + h ) * DH + c];
        Ks[c][r] = g_k[((size_t)(b * SEQ + t0 + r) * NHKV + hk) * DH + c];
    }
    __syncthreads();
    float acc[4][4];
#pragma unroll
    for (int i = 0; i < 4; i++)
#pragma unroll
        for (int j = 0; j < 4; j++) acc[i][j] = 0.f;
#pragma unroll 16
    for (int d = 0; d < 64; d++) {
        float4 a  = *(const float4*)&Qs[d][ty * 4];
        float4 b4 = *(const float4*)&Ks[d][tx * 4];
        float av[4] = {a.x, a.y, a.z, a.w};
        float bv[4] = {b4.x, b4.y, b4.z, b4.w};
#pragma unroll
        for (int i = 0; i < 4; i++)
#pragma unroll
            for (int j = 0; j < 4; j++)
                acc[i][j] = fmaf(av[i], bv[j], acc[i][j]);
    }
    float* outp = g_sc + ((size_t)bh * SEQ + s0) * SEQ + t0;
#pragma unroll
    for (int i = 0; i < 4; i++)
#pragma unroll
        for (int j = 0; j < 4; j++)
            outp[(size_t)(ty * 4 + i) * SEQ + tx * 4 + j] = acc[i][j] * 0.125f;
}

// ---------------- softmax ----------------
__global__ void __launch_bounds__(256) k_softmax()
{
    float* p = g_sc + (size_t)blockIdx.x * SEQ;
    const int tid = threadIdx.x;
    float a = p[tid], b = p[tid + 256];
    __shared__ float red[256];
    red[tid] = fmaxf(a, b); __syncthreads();
    for (int s = 128; s > 0; s >>= 1) {
        if (tid < s) red[tid] = fmaxf(red[tid], red[tid + s]);
        __syncthreads();
    }
    const float m = red[0];
    __syncthreads();
    float ea = __expf(a - m), eb = __expf(b - m);
    red[tid] = ea + eb; __syncthreads();
    for (int s = 128; s > 0; s >>= 1) {
        if (tid < s) red[tid] += red[tid + s];
        __syncthreads();
    }
    const float inv = 1.f / red[0];
    p[tid] = ea * inv;
    p[tid + 256] = eb * inv;
}

// ---------------- attention: O = P @ V (SIMT) ----------------
__global__ void __launch_bounds__(256) k_attn_pv()
{
    const int bh = blockIdx.y;
    const int b = bh / NHQ, h = bh % NHQ, hk = h / GRP;
    const int s0 = blockIdx.x * 64;
    __shared__ float Ps[64][68];
    __shared__ float Vs[64][68];
    const int tid = threadIdx.x, tx = tid & 15, ty = tid >> 4;
    float acc[4][4];
#pragma unroll
    for (int i = 0; i < 4; i++)
#pragma unroll
        for (int j = 0; j < 4; j++) acc[i][j] = 0.f;
    const float* srow = g_sc + ((size_t)bh * SEQ + s0) * SEQ;
    for (int t0 = 0; t0 < SEQ; t0 += 64) {
#pragma unroll
        for (int l = 0; l < 16; l++) {
            int idx = tid + l * 256;
            int r = idx >> 6, c = idx & 63;
            Ps[c][r] = srow[(size_t)r * SEQ + t0 + c];
            Vs[r][c] = g_v[((size_t)(b * SEQ + t0 + r) * NHKV + hk) * DH + c];
        }
        __syncthreads();
#pragma unroll 16
        for (int t = 0; t < 64; t++) {
            float4 a  = *(const float4*)&Ps[t][ty * 4];
            float4 b4 = *(const float4*)&Vs[t][tx * 4];
            float av[4] = {a.x, a.y, a.z, a.w};
            float bv[4] = {b4.x, b4.y, b4.z, b4.w};
#pragma unroll
            for (int i = 0; i < 4; i++)
#pragma unroll
                for (int j = 0; j < 4; j++)
                    acc[i][j] = fmaf(av[i], bv[j], acc[i][j]);
        }
        __syncthreads();
    }
#pragma unroll
    for (int i = 0; i < 4; i++) {
        int s = s0 + ty * 4 + i;
#pragma unroll
        for (int j = 0; j < 4; j++) {
            int d = tx * 4 + j;
            g_ao[((size_t)(b * SEQ + s) * NHQ + h) * DH + d] = acc[i][j];
        }
    }
}

// ---------------- router ----------------
__global__ void k_zero() { if (threadIdx.x < NE) g_cnt[threadIdx.x] = 0; }

__global__ void __launch_bounds__(256) k_router(const float* __restrict__ rw,
                                                const float* __restrict__ rb)
{
    const int t = blockIdx.x;
    const float* x = g_t + (size_t)t * HD;
    const int tid = threadIdx.x;
    const int e = tid & 7, ch = tid >> 3;
    float s = 0.f;
    const int base = ch * 32;
    for (int i = base; i < base + 32; i++) s += x[i] * rw[i * NE + e];
    __shared__ float part[32][9];
    __shared__ float sl[8];
    part[ch][e] = s; __syncthreads();
    if (tid < 8) {
        float l = rb[tid];
        for (int c2 = 0; c2 < 32; c2++) l += part[c2][tid];
        sl[tid] = l;
    }
    __syncthreads();
    if (tid == 0) {
        int e0 = 0; float v0 = sl[0];
        for (int i = 1; i < 8; i++) if (sl[i] > v0) { v0 = sl[i]; e0 = i; }
        int e1 = -1; float v1 = -3.402823e38f;
        for (int i = 0; i < 8; i++) {
            if (i == e0) continue;
            if (sl[i] > v1) { v1 = sl[i]; e1 = i; }
        }
        const float z = __expf(v1 - v0);
        const float p0 = 1.f / (1.f + z);
        const float p1 = z   / (1.f + z);
        const int r0 = atomicAdd(&g_cnt[e0], 1);
        const int r1 = atomicAdd(&g_cnt[e1], 1);
        g_rows[e0 * TB + r0] = t;
        g_rows[e1 * TB + r1] = t;
        g_se[t * 2 + 0] = e0; g_sr[t * 2 + 0] = r0; g_sp[t * 2 + 0] = p0;
        g_se[t * 2 + 1] = e1; g_sr[t * 2 + 1] = r1; g_sp[t * 2 + 1] = p1;
    }
}

// ---------------- MoE gate or up GEMM (gathered rows, tf32 MMA) ----------------
__global__ void __launch_bounds__(256) k_moe_gu(const float* __restrict__ W, int which)
{
    const int e = blockIdx.z;
    const int cnt = g_cnt[e];
    const int rm = blockIdx.y * 128;
    if (rm >= cnt) return;
    const int bn = blockIdx.x * 128;

    __shared__ uint32_t As[2 * AS_STAGE];
    __shared__ uint32_t Bs[2 * BS_STAGE];
    __shared__ int srow[128];
    const int tid = threadIdx.x;
    if (tid < 128) {
        int rr = rm + tid;
        srow[tid] = (rr < cnt) ? g_rows[e * TB + rr] : 0;
    }
    __syncthreads();

    float acc[4][4][4];
    gemm_mainloop(acc, g_t, HD, srow, 0, W + (size_t)e * HD * ID, ID, bn, HD, As, Bs);

    float* out = which ? g_act : g_gt;
    EPI_LOOP({
        const int r = rm + row_l;
        if (r < cnt) {
            const int c = bn + col_l;
            out[((size_t)e * TB + r) * ID + c] = val;
        }
    })
}

// ---------------- silu(g+gb) * (u+ub) (in-place into g_act) ----------------
__global__ void __launch_bounds__(256) k_silu(const float* __restrict__ gb,
                                              const float* __restrict__ ub)
{
    const int e = blockIdx.y;
    const int cnt = g_cnt[e];
    const int rm = blockIdx.x * 128;
    if (rm >= cnt) return;
    const int tid = threadIdx.x;
    const int rend = min(cnt - rm, 128);
    for (int rr = 0; rr < rend; rr++) {
        const size_t rowoff = ((size_t)e * TB + rm + rr) * ID;
        for (int c4 = tid; c4 < ID / 4; c4 += 256) {
            const int c = c4 * 4;
            float4 g = *(const float4*)(g_gt + rowoff + c);
            float4 u = *(const float4*)(g_act + rowoff + c);
            float4 bgv = *(const float4*)(gb + (size_t)e * ID + c);
            float4 buv = *(const float4*)(ub + (size_t)e * ID + c);
            float gx = g.x + bgv.x, gy = g.y + bgv.y, gz = g.z + bgv.z, gw2 = g.w + bgv.w;
            float4 o;
            o.x = (gx / (1.f + __expf(-gx))) * (u.x + buv.x);
            o.y = (gy / (1.f + __expf(-gy))) * (u.y + buv.y);
            o.z = (gz / (1.f + __expf(-gz))) * (u.z + buv.z);
            o.w = (gw2 / (1.f + __expf(-gw2))) * (u.w + buv.w);
            *(float4*)(g_act + rowoff + c) = o;
        }
    }
}

// ---------------- MoE down GEMM (packed rows, tf32 MMA) ----------------
__global__ void __launch_bounds__(256) k_down(const float* __restrict__ dw,
                                              const float* __restrict__ db)
{
    const int e = blockIdx.z;
    const int cnt = g_cnt[e];
    const int rm = blockIdx.y * 128;
    if (rm >= cnt) return;
    const int bn = blockIdx.x * 128;

    __shared__ uint32_t As[2 * AS_STAGE];
    __shared__ uint32_t Bs[2 * BS_STAGE];

    float acc[4][4][4];
    gemm_mainloop(acc, g_act + (size_t)e * TB * ID, ID, nullptr, rm,
                  dw + (size_t)e * ID * HD, HD, bn, ID, As, Bs);

    EPI_LOOP({
        const int r = rm + row_l;
        if (r < cnt) {
            const int c = bn + col_l;
            g_dn[((size_t)e * TB + r) * HD + c] = val + db[(size_t)e * HD + c];
        }
    })
}

// ---------------- combine ----------------
__global__ void __launch_bounds__(256) k_combine(float* __restrict__ out)
{
    const int t = blockIdx.x;
    const int tid = threadIdx.x;
    const int e0 = g_se[t * 2 + 0], r0 = g_sr[t * 2 + 0];
    const int e1 = g_se[t * 2 + 1], r1 = g_sr[t * 2 + 1];
    const float p0 = g_sp[t * 2 + 0], p1 = g_sp[t * 2 + 1];
    const float* d0 = g_dn + ((size_t)e0 * TB + r0) * HD;
    const float* d1 = g_dn + ((size_t)e1 * TB + r1) * HD;
    const float* xr = g_x2 + (size_t)t * HD;
    for (int i = tid; i < HD; i += 256)
        out[(size_t)t * HD + i] = xr[i] + p0 * d0[i] + p1 * d1[i];
}

// ---------------- launcher ----------------
extern "C" void kernel_launch(void* const* d_in, const int* in_sizes, int n_in,
                              void* d_out, int out_size)
{
    (void)in_sizes; (void)n_in; (void)out_size;
    const float* x   = (const float*)d_in[0];
    const float* n1w = (const float*)d_in[1];
    const float* qw  = (const float*)d_in[2];
    const float* qb  = (const float*)d_in[3];
    const float* kw  = (const float*)d_in[4];
    const float* kb  = (const float*)d_in[5];
    const float* vw  = (const float*)d_in[6];
    const float* vb  = (const float*)d_in[7];
    const float* ow  = (const float*)d_in[8];
    const float* ob  = (const float*)d_in[9];
    const float* n2w = (const float*)d_in[10];
    const float* rw  = (const float*)d_in[11];
    const float* rb  = (const float*)d_in[12];
    const float* gw  = (const float*)d_in[13];
    const float* gb  = (const float*)d_in[14];
    const float* uw  = (const float*)d_in[15];
    const float* ub  = (const float*)d_in[16];
    const float* dw  = (const float*)d_in[17];
    const float* db  = (const float*)d_in[18];
    float* out = (float*)d_out;

    k_rms1<<<TB, 256>>>(x, n1w);
    k_qkv<<<dim3(12, 8), 256>>>(qw, qb, kw, kb, vw, vb);
    k_attn_scores<<<dim3(SEQ / 64, SEQ / 64, NB * NHQ), 256>>>();
    k_softmax<<<NB * NHQ * SEQ, 256>>>();
    k_attn_pv<<<dim3(SEQ / 64, NB * NHQ), 256>>>();
    k_oproj<<<dim3(8, 8), 256>>>(ow, ob, x);
    k_rms2<<<TB, 256>>>(n2w);
    k_zero<<<1, 32>>>();
    k_router<<<TB, 256>>>(rw, rb);
    k_moe_gu<<<dim3(ID / 128, TB / 128, NE), 256>>>(gw, 0);
    k_moe_gu<<<dim3(ID / 128, TB / 128, NE), 256>>>(uw, 1);
    k_silu<<<dim3(TB / 128, NE), 256>>>(gb, ub);
    k_down<<<dim3(HD / 128, TB / 128, NE), 256>>>(dw, db);
    k_combine<<<TB, 256>>>(out);
}